// round 7
// baseline (speedup 1.0000x reference)
#include <cuda_runtime.h>

// Inverse discrete Hough transform, round 7 (= round 6 + merge-stride fix):
//  - single-angle loop, 2 chains of 4 px -> 4 CTAs/SM (32 warps)
//  - pass-B staging buffer is PIXEL-major [pix][nc]: contiguous 512B stores;
//    pass A folds the merge in-register via coalesced reads (stride fixed:
//    consecutive strip pixels are 256 pBT-pixels apart, not 1)
//  - offset tables preloaded to SMEM per CTA
// out[nc,y,x] = sum_a accT[a*400+r(a,y,x)][nc]
// Pass B: angles 0..44 & 135..179, strips along y -> pBT[x*256+y][nc]
// Pass A: angles 45..134, strips along x, += pBT, -> out

#define NA 180
#define NR 400
#define NC 256
#define OH 256
#define OW 256
#define AR (NA * NR)      // 72000
#define HW (OH * OW)      // 65536
#define NSTRIP 8192       // 65536 px / 8 per strip

typedef unsigned long long ull;

__device__ float  g_accT[AR * NC];                   // 73.7 MB: [a*400+r][nc]
__device__ float2 g_trig[NA];
__device__ unsigned g_offA[(size_t)NSTRIP * 90 * 8]; // [strip][arel][p] byte offsets
__device__ unsigned g_offB[(size_t)NSTRIP * 90 * 8];
__device__ ull    g_pBT[HW * NC / 2];                // pass-B partial, [x*256+y][nc/2]

__device__ __forceinline__ ull fadd2(ull a, ull b) {
    ull r;
    asm("add.rn.f32x2 %0, %1, %2;" : "=l"(r) : "l"(a), "l"(b));
    return r;
}
__device__ __forceinline__ float u64lo(ull u) {
    float a, b; asm("mov.b64 {%0,%1}, %2;" : "=f"(a), "=f"(b) : "l"(u)); return a;
}
__device__ __forceinline__ float u64hi(ull u) {
    float a, b; asm("mov.b64 {%0,%1}, %2;" : "=f"(a), "=f"(b) : "l"(u)); return b;
}

// unconditional 16B gather
#define LDG2(v0, v1, addr)                                             \
    asm("ld.global.nc.v2.u64 {%0,%1}, [%2];"                           \
        : "=l"(v0), "=l"(v1) : "l"(addr))
// predicated gather: load only if oc != op (else keep previous registers)
#define PLDG2(v0, v1, oc, op, addr)                                    \
    asm("{\n\t.reg .pred q;\n\tsetp.ne.u32 q, %2, %3;\n\t"             \
        "@q ld.global.nc.v2.u64 {%0,%1}, [%4];\n\t}"                   \
        : "+l"(v0), "+l"(v1) : "r"(oc), "r"(op), "l"(addr))

__global__ void k_trig() {
    int a = threadIdx.x;
    if (a < NA) {
        // f32 theta (rn multiply), then correctly-rounded f32 cos/sin via
        // double (immune to fast-math; matches the JAX reference bit-exactly).
        float t = __fmul_rn((float)a, (float)(3.14159265358979323846 / 180.0));
        double td = (double)t;
        g_trig[a] = make_float2((float)cos(td), (float)sin(td));
    }
}

// 32x32 tiled transpose of acc[256][72000] -> g_accT[72000][256]
__global__ void k_transpose(const float* __restrict__ in) {
    __shared__ float tile[32][33];
    int tx = threadIdx.x, ty = threadIdx.y;           // 32 x 8
    int ar = blockIdx.x * 32 + tx;
#pragma unroll
    for (int k = 0; k < 4; k++)
        tile[ty + k * 8][tx] = in[(size_t)(blockIdx.y * 32 + ty + k * 8) * AR + ar];
    __syncthreads();
    int nc2 = blockIdx.y * 32 + tx;
#pragma unroll
    for (int k = 0; k < 4; k++)
        g_accT[(size_t)(blockIdx.x * 32 + ty + k * 8) * NC + nc2] = tile[tx][ty + k * 8];
}

// Precompute exact rho byte-offset tables: [strip][arel][p].
__global__ void k_tab() {
    int idx = blockIdx.x * 256 + threadIdx.x;   // 180 * 65536 threads
    int p = idx & 7;
    int s = (idx >> 3) & (NSTRIP - 1);
    int a = idx >> 16;
    bool isA = (a >= 45 && a < 135);
    int line = s >> 5, q0 = (s & 31) << 3;
    int x = isA ? (q0 + p) : line;
    int y = isA ? line : (q0 + p);
    float2 cs = g_trig[a];
    // exact reference arithmetic: rn(rn(xc*cos) + rn(yc*sin)), round-half-even
    float sum = __fadd_rn(__fmul_rn((float)(x - OW / 2), cs.x),
                          __fmul_rn((float)(y - OH / 2), cs.y));
    unsigned off = (unsigned)(a * NR + __float2int_rn(sum) + NR / 2) << 10;
    int arel = isA ? (a - 45) : (a < 45 ? a : a - 90);
    unsigned* tab = isA ? g_offA : g_offB;
    tab[((size_t)s * 90 + arel) * 8 + p] = off;
}

// Main pass. CTA = 8 warps = 4 strips x 2 channel-halves; tables in SMEM.
// PASS=1: y-strips, store pixel-major g_pBT (512B-contiguous per pixel).
// PASS=0: x-strips, fold g_pBT in-register (coalesced 512B/warp per px).
template <int PASS>
__global__ __launch_bounds__(256, 4) void k_pass(float* __restrict__ outp) {
    __shared__ uint4 stab[720];          // 4 strips x 90 angles x (8 off = 2 uint4)

    const unsigned* tab = (PASS == 0) ? g_offA : g_offB;
    int tid = threadIdx.x;
    {
        const uint4* gsrc = (const uint4*)(tab + (size_t)blockIdx.x * 4 * 90 * 8);
        stab[tid] = __ldg(gsrc + tid);
        stab[tid + 256] = __ldg(gsrc + tid + 256);
        int j = tid + 512;
        if (j < 720) stab[j] = __ldg(gsrc + j);
    }
    __syncthreads();

    int w = tid >> 5, l = tid & 31;
    int half = w & 1, sl = w >> 1;       // strip-local 0..3
    int s = blockIdx.x * 4 + sl;
    int line = s >> 5, q0 = (s & 31) << 3;

    ull base;
    {
        const char* gp = (const char*)g_accT + half * 512 + l * 16;
        asm("cvta.to.global.u64 %0, %1;" : "=l"(base) : "l"(gp));
    }

    // pixel p -> acc[2p] (channels c0,c0+1), acc[2p+1] (c0+2,c0+3)
    ull acc[16];
#pragma unroll
    for (int i = 0; i < 16; i++) acc[i] = 0ull;

    const uint4* tp = &stab[sl * 180];

    for (int a = 0; a < 90; a++) {
        uint4 A0 = tp[0], A1 = tp[1];    // px0-3, px4-7
        tp += 2;
        ull v0, v1, u0, u1;
        LDG2(v0, v1, base + A0.x);
        LDG2(u0, u1, base + A1.x);
        acc[0] = fadd2(acc[0], v0);  acc[1] = fadd2(acc[1], v1);
        acc[8] = fadd2(acc[8], u0);  acc[9] = fadd2(acc[9], u1);
        PLDG2(v0, v1, A0.y, A0.x, base + A0.y);
        PLDG2(u0, u1, A1.y, A1.x, base + A1.y);
        acc[2]  = fadd2(acc[2],  v0); acc[3]  = fadd2(acc[3],  v1);
        acc[10] = fadd2(acc[10], u0); acc[11] = fadd2(acc[11], u1);
        PLDG2(v0, v1, A0.z, A0.y, base + A0.z);
        PLDG2(u0, u1, A1.z, A1.y, base + A1.z);
        acc[4]  = fadd2(acc[4],  v0); acc[5]  = fadd2(acc[5],  v1);
        acc[12] = fadd2(acc[12], u0); acc[13] = fadd2(acc[13], u1);
        PLDG2(v0, v1, A0.w, A0.z, base + A0.w);
        PLDG2(u0, u1, A1.w, A1.z, base + A1.w);
        acc[6]  = fadd2(acc[6],  v0); acc[7]  = fadd2(acc[7],  v1);
        acc[14] = fadd2(acc[14], u0); acc[15] = fadd2(acc[15], u1);
    }

    if (PASS == 1) {
        // pixel-major staging: pix = x*256+y = line*256 + (q0+p)
        // consecutive p -> consecutive pixels (stride 128 ull)
        ull* pw = g_pBT + ((size_t)line * 256 + q0) * 128 + half * 64 + l * 2;
#pragma unroll
        for (int p = 0; p < 8; p++)
            *reinterpret_cast<ulonglong2*>(pw + (size_t)p * 128) =
                make_ulonglong2(acc[2 * p], acc[2 * p + 1]);
        return;
    }

    // PASS A: fold pass-B partials. pix = (q0+p)*256 + line:
    // consecutive p -> 256 pixels apart = 256*128 ull (FIXED stride).
    {
        const ull* pr = g_pBT + ((size_t)q0 * 256 + line) * 128 + half * 64 + l * 2;
#pragma unroll
        for (int p = 0; p < 8; p++) {
            ulonglong2 b = __ldg(reinterpret_cast<const ulonglong2*>(
                pr + (size_t)p * 256 * 128));
            acc[2 * p]     = fadd2(acc[2 * p],     b.x);
            acc[2 * p + 1] = fadd2(acc[2 * p + 1], b.y);
        }
    }

    // store out[nc][y][x]: lane channels chb..chb+3, 8 px contiguous
    int chb = half * 128 + l * 4;
    float* op = outp + (size_t)chb * HW + (line << 8) + q0;
#pragma unroll
    for (int j = 0; j < 4; j++) {
        float t[8];
#pragma unroll
        for (int p = 0; p < 8; p++) {
            ull u = acc[2 * p + (j >> 1)];
            t[p] = (j & 1) ? u64hi(u) : u64lo(u);
        }
        float4* q = (float4*)(op + (size_t)j * HW);
        q[0] = make_float4(t[0], t[1], t[2], t[3]);
        q[1] = make_float4(t[4], t[5], t[6], t[7]);
    }
}

extern "C" void kernel_launch(void* const* d_in, const int* in_sizes, int n_in,
                              void* d_out, int out_size) {
    const float* acc = (const float*)d_in[0];
    float* out = (float*)d_out;

    k_trig<<<1, 192>>>();
    k_transpose<<<dim3(AR / 32, NC / 32), dim3(32, 8)>>>(acc);
    k_tab<<<NA * HW / 256, 256>>>();          // 46080 blocks
    k_pass<1><<<2048, 256>>>(out);            // pass B -> g_pBT (pixel-major)
    k_pass<0><<<2048, 256>>>(out);            // pass A: += pBT, -> out
}